// round 1
// baseline (speedup 1.0000x reference)
#include <cuda_runtime.h>
#include <math.h>

#define Bb   8
#define Ss   1024
#define Dd   768
#define Hh   12
#define HDd  64
#define HIDh 3072
#define Mm   (Bb*Ss)   // 8192

// ---------------- scratch (device globals; no allocs allowed) ----------------
__device__ float g_q  [(size_t)Mm*Dd];
__device__ float g_k  [(size_t)Mm*Dd];
__device__ float g_v  [(size_t)Mm*Dd];
__device__ float g_ctx[(size_t)Mm*Dd];
__device__ float g_y  [(size_t)Mm*Dd];
__device__ float g_ln2[(size_t)Mm*Dd];
__device__ float g_h1 [(size_t)Mm*HIDh];

__device__ __forceinline__ float gelu_exact(float x) {
    return 0.5f * x * (1.0f + erff(x * 0.70710678118654752f));
}

// ---------------- QKV GEMM: q/k/v = x @ W + b, written as [B,H,S,HD] --------
// 64x64 tile, BK=16, 256 threads, 4x4 micro-tile. gridDim.z selects q/k/v.
__global__ __launch_bounds__(256) void qkv_gemm(
    const float* __restrict__ x,
    const float* __restrict__ wq, const float* __restrict__ bq,
    const float* __restrict__ wk, const float* __restrict__ bk,
    const float* __restrict__ wv, const float* __restrict__ bv)
{
    const int which = blockIdx.z;
    const float* Bm   = which == 0 ? wq : (which == 1 ? wk : wv);
    const float* bias = which == 0 ? bq : (which == 1 ? bk : bv);
    float* out        = which == 0 ? g_q : (which == 1 ? g_k : g_v);

    const int K = Dd, N = Dd;
    __shared__ float As[16][64];
    __shared__ float Bs[16][64];

    int tid = threadIdx.x;
    int tx = tid & 15, ty = tid >> 4;
    int m0 = blockIdx.y * 64, n0 = blockIdx.x * 64;

    float acc[4][4] = {};
    for (int k0 = 0; k0 < K; k0 += 16) {
        #pragma unroll
        for (int l = 0; l < 4; l++) {
            int e = tid + l * 256;
            int r = e >> 4, c = e & 15;
            As[c][r] = x[(size_t)(m0 + r) * K + k0 + c];
        }
        #pragma unroll
        for (int l = 0; l < 4; l++) {
            int e = tid + l * 256;
            int r = e >> 6, c = e & 63;
            Bs[r][c] = Bm[(size_t)(k0 + r) * N + n0 + c];
        }
        __syncthreads();
        #pragma unroll
        for (int kk = 0; kk < 16; kk++) {
            float a[4], b[4];
            #pragma unroll
            for (int i = 0; i < 4; i++) a[i] = As[kk][ty * 4 + i];
            #pragma unroll
            for (int j = 0; j < 4; j++) b[j] = Bs[kk][tx * 4 + j];
            #pragma unroll
            for (int i = 0; i < 4; i++)
                #pragma unroll
                for (int j = 0; j < 4; j++)
                    acc[i][j] += a[i] * b[j];
        }
        __syncthreads();
    }
    #pragma unroll
    for (int i = 0; i < 4; i++) {
        int m = m0 + ty * 4 + i;
        int b = m >> 10, s = m & 1023;
        #pragma unroll
        for (int j = 0; j < 4; j++) {
            int n = n0 + tx * 4 + j;
            int h = n >> 6, hd = n & 63;
            float val = acc[i][j] + bias[n];
            out[((((size_t)b * Hh + h) * Ss) + s) * HDd + hd] = val;
        }
    }
}

// ---------------- MLP GEMM: C = [res +] act(A @ Bm + bias) ------------------
// mode 0: A=g_ln2 [M,768], Bm=w_in [768,3072], gelu -> g_h1
// mode 1: A=g_h1 [M,3072], Bm=w_out [3072,768], gelu, +g_y -> d_out
__global__ __launch_bounds__(256) void mlp_gemm(
    const float* __restrict__ Bm, const float* __restrict__ bias,
    float* __restrict__ outParam, int mode)
{
    const float* A   = (mode == 0) ? g_ln2 : g_h1;
    float*       C   = (mode == 0) ? g_h1  : outParam;
    const float* res = (mode == 0) ? nullptr : g_y;
    const int N = (mode == 0) ? HIDh : Dd;
    const int K = (mode == 0) ? Dd   : HIDh;

    __shared__ float As[16][64];
    __shared__ float Bs[16][64];

    int tid = threadIdx.x;
    int tx = tid & 15, ty = tid >> 4;
    int m0 = blockIdx.y * 64, n0 = blockIdx.x * 64;

    float acc[4][4] = {};
    for (int k0 = 0; k0 < K; k0 += 16) {
        #pragma unroll
        for (int l = 0; l < 4; l++) {
            int e = tid + l * 256;
            int r = e >> 4, c = e & 15;
            As[c][r] = A[(size_t)(m0 + r) * K + k0 + c];
        }
        #pragma unroll
        for (int l = 0; l < 4; l++) {
            int e = tid + l * 256;
            int r = e >> 6, c = e & 63;
            Bs[r][c] = Bm[(size_t)(k0 + r) * N + n0 + c];
        }
        __syncthreads();
        #pragma unroll
        for (int kk = 0; kk < 16; kk++) {
            float a[4], b[4];
            #pragma unroll
            for (int i = 0; i < 4; i++) a[i] = As[kk][ty * 4 + i];
            #pragma unroll
            for (int j = 0; j < 4; j++) b[j] = Bs[kk][tx * 4 + j];
            #pragma unroll
            for (int i = 0; i < 4; i++)
                #pragma unroll
                for (int j = 0; j < 4; j++)
                    acc[i][j] += a[i] * b[j];
        }
        __syncthreads();
    }
    #pragma unroll
    for (int i = 0; i < 4; i++) {
        int m = m0 + ty * 4 + i;
        #pragma unroll
        for (int j = 0; j < 4; j++) {
            int n = n0 + tx * 4 + j;
            float val = gelu_exact(acc[i][j] + bias[n]);
            if (res) val += res[(size_t)m * N + n];
            C[(size_t)m * N + n] = val;
        }
    }
}

// ---------------- Attention: flash-style, 1 thread = 1 query row ------------
// grid: (S/128, B*H), block 128. K/V tiled 16 rows through shared memory.
__global__ __launch_bounds__(128) void attn_kernel(void)
{
    const int bh = blockIdx.y;
    const int tid = threadIdx.x;
    const int qrow = blockIdx.x * 128 + tid;

    const float* qp = g_q + ((size_t)bh * Ss + qrow) * HDd;
    const float* kbase = g_k + (size_t)bh * Ss * HDd;
    const float* vbase = g_v + (size_t)bh * Ss * HDd;

    float qr[HDd];
    #pragma unroll
    for (int d = 0; d < HDd; d++) qr[d] = qp[d];

    float acc[HDd] = {};
    float mi = -1e30f, li = 0.0f;

    __shared__ float Ks[16][HDd];
    __shared__ float Vs[16][HDd];

    for (int kt = 0; kt < Ss / 16; kt++) {
        const float* kp = kbase + (size_t)kt * 16 * HDd;
        const float* vp = vbase + (size_t)kt * 16 * HDd;
        #pragma unroll
        for (int l = 0; l < 8; l++) {
            int e = tid + l * 128;
            Ks[e >> 6][e & 63] = kp[e];
            Vs[e >> 6][e & 63] = vp[e];
        }
        __syncthreads();

        float sc[16];
        float tmax = -1e30f;
        #pragma unroll
        for (int j = 0; j < 16; j++) {
            float dot = 0.0f;
            #pragma unroll
            for (int d = 0; d < HDd; d++) dot += qr[d] * Ks[j][d];
            sc[j] = dot * 0.125f;           // * HD^-0.5
            tmax = fmaxf(tmax, sc[j]);
        }
        float mnew = fmaxf(mi, tmax);
        float corr = __expf(mi - mnew);
        li *= corr;
        #pragma unroll
        for (int d = 0; d < HDd; d++) acc[d] *= corr;
        #pragma unroll
        for (int j = 0; j < 16; j++) {
            float p = __expf(sc[j] - mnew);
            li += p;
            #pragma unroll
            for (int d = 0; d < HDd; d++) acc[d] += p * Vs[j][d];
        }
        mi = mnew;
        __syncthreads();
    }
    float inv = 1.0f / li;
    float* op = g_ctx + ((size_t)bh * Ss + qrow) * HDd;
    #pragma unroll
    for (int d = 0; d < HDd; d++) op[d] = acc[d] * inv;
}

// ---------------- LN1: y = x + LN(ctx[B,H,S,HD]) * g + b --------------------
__global__ __launch_bounds__(256) void ln1_add(
    const float* __restrict__ x, const float* __restrict__ g,
    const float* __restrict__ bta)
{
    const int row = blockIdx.x;           // token index
    const int b = row >> 10, s = row & 1023;
    const int tid = threadIdx.x;

    float vals[3];
    float sum = 0.0f, sq = 0.0f;
    #pragma unroll
    for (int i = 0; i < 3; i++) {
        int col = tid + i * 256;
        int h = col >> 6, hd = col & 63;
        float c = g_ctx[(((size_t)b * Hh + h) * Ss + s) * HDd + hd];
        vals[i] = c;
        sum += c;
        sq += c * c;
    }
    __shared__ float rs[256], rq[256];
    rs[tid] = sum; rq[tid] = sq;
    __syncthreads();
    for (int o = 128; o > 0; o >>= 1) {
        if (tid < o) { rs[tid] += rs[tid + o]; rq[tid] += rq[tid + o]; }
        __syncthreads();
    }
    float mu = rs[0] * (1.0f / Dd);
    float var = rq[0] * (1.0f / Dd) - mu * mu;
    float rstd = rsqrtf(var + 1e-5f);
    #pragma unroll
    for (int i = 0; i < 3; i++) {
        int col = tid + i * 256;
        float yv = x[(size_t)row * Dd + col] +
                   (vals[i] - mu) * rstd * g[col] + bta[col];
        g_y[(size_t)row * Dd + col] = yv;
    }
}

// ---------------- LN2: g_ln2 = LN(g_y) * g + b ------------------------------
__global__ __launch_bounds__(256) void ln2_kernel(
    const float* __restrict__ g, const float* __restrict__ bta)
{
    const int row = blockIdx.x;
    const int tid = threadIdx.x;

    float vals[3];
    float sum = 0.0f, sq = 0.0f;
    #pragma unroll
    for (int i = 0; i < 3; i++) {
        int col = tid + i * 256;
        float c = g_y[(size_t)row * Dd + col];
        vals[i] = c;
        sum += c;
        sq += c * c;
    }
    __shared__ float rs[256], rq[256];
    rs[tid] = sum; rq[tid] = sq;
    __syncthreads();
    for (int o = 128; o > 0; o >>= 1) {
        if (tid < o) { rs[tid] += rs[tid + o]; rq[tid] += rq[tid + o]; }
        __syncthreads();
    }
    float mu = rs[0] * (1.0f / Dd);
    float var = rq[0] * (1.0f / Dd) - mu * mu;
    float rstd = rsqrtf(var + 1e-5f);
    #pragma unroll
    for (int i = 0; i < 3; i++) {
        int col = tid + i * 256;
        g_ln2[(size_t)row * Dd + col] = (vals[i] - mu) * rstd * g[col] + bta[col];
    }
}

// ---------------- launch ----------------------------------------------------
extern "C" void kernel_launch(void* const* d_in, const int* in_sizes, int n_in,
                              void* d_out, int out_size)
{
    (void)in_sizes; (void)n_in; (void)out_size;
    const float* x     = (const float*)d_in[0];
    const float* wq    = (const float*)d_in[1];
    const float* bq    = (const float*)d_in[2];
    const float* wk    = (const float*)d_in[3];
    const float* bk    = (const float*)d_in[4];
    const float* wv    = (const float*)d_in[5];
    const float* bv    = (const float*)d_in[6];
    const float* ln1_g = (const float*)d_in[7];
    const float* ln1_b = (const float*)d_in[8];
    const float* ln2_g = (const float*)d_in[9];
    const float* ln2_b = (const float*)d_in[10];
    const float* w_in  = (const float*)d_in[11];
    const float* b_in  = (const float*)d_in[12];
    const float* w_out = (const float*)d_in[13];
    const float* b_out = (const float*)d_in[14];
    float* out = (float*)d_out;

    // 1) QKV projections -> [B,H,S,HD]
    dim3 gq(Dd / 64, Mm / 64, 3);
    qkv_gemm<<<gq, 256>>>(x, wq, bq, wk, bk, wv, bv);

    // 2) attention -> g_ctx [B,H,S,HD]
    dim3 ga(Ss / 128, Bb * Hh);
    attn_kernel<<<ga, 128>>>();

    // 3) y = x + LN1(ctx)
    ln1_add<<<Mm, 256>>>(x, ln1_g, ln1_b);

    // 4) ln2 = LN2(y)
    ln2_kernel<<<Mm, 256>>>(ln2_g, ln2_b);

    // 5) h1 = gelu(ln2 @ w_in + b_in)
    dim3 g1(HIDh / 64, Mm / 64);
    mlp_gemm<<<g1, 256>>>(w_in, b_in, nullptr, 0);

    // 6) out = y + gelu(h1 @ w_out + b_out)
    dim3 g2(Dd / 64, Mm / 64);
    mlp_gemm<<<g2, 256>>>(w_out, b_out, out, 1);
}

// round 2
// speedup vs baseline: 2.7328x; 2.7328x over previous
#include <cuda_runtime.h>
#include <math.h>
#include <stdint.h>

#define Bb   8
#define Ss   1024
#define Dd   768
#define Hh   12
#define HDd  64
#define HIDh 3072
#define Mm   (Bb*Ss)   // 8192

// ---------------- scratch (device globals; no allocs allowed) ----------------
__device__ float g_q  [(size_t)Mm*Dd];
__device__ float g_k  [(size_t)Mm*Dd];
__device__ float g_v  [(size_t)Mm*Dd];
__device__ float g_ctx[(size_t)Mm*Dd];
__device__ float g_y  [(size_t)Mm*Dd];
__device__ float g_ln2[(size_t)Mm*Dd];
__device__ float g_h1 [(size_t)Mm*HIDh];

__device__ __forceinline__ float gelu_exact(float x) {
    return 0.5f * x * (1.0f + erff(x * 0.70710678118654752f));
}

__device__ __forceinline__ uint32_t f2tf32(float f) {
    uint32_t r;
    asm("cvt.rna.tf32.f32 %0, %1;" : "=r"(r) : "f"(f));
    return r;
}

__device__ __forceinline__ void cp_async16(uint32_t saddr, const float* gaddr) {
    asm volatile("cp.async.cg.shared.global [%0], [%1], 16;\n" :: "r"(saddr), "l"(gaddr));
}

// =====================================================================
// TF32 tensor-core GEMM: C[M,N] = epilogue(A[M,K] @ W[K,N] + bias)
// BM=128, BN=128, BK=16, 256 threads (8 warps as 2x4), warp tile 64x32,
// per-warp 4x4 grid of m16n8k8 mma. Double-buffered cp.async.
//
// MODE 0: A = x (param). out = g_q/g_k/g_v by `which`, scattered [B,H,S,HD]
// MODE 1: A = g_ln2.   out = g_h1, val = gelu(acc + bias)
// MODE 2: A = g_h1.    out = Cout (d_out), val = gelu(acc+bias) + g_y
// =====================================================================
#define ASTRIDE 20    // 16 + 4 pad (floats); 80B row, 16B aligned
#define BSTRIDE 136   // 128 + 8 pad (floats); 544B row, 16B aligned

template<int MODE>
__global__ __launch_bounds__(256) void gemm_tf32(
    const float* __restrict__ Ain, const float* __restrict__ Bw,
    const float* __restrict__ bias, float* __restrict__ Cout,
    int N, int K, int which)
{
    __shared__ float As[2][128 * ASTRIDE];
    __shared__ float Bs[2][16 * BSTRIDE];

    const float* A = (MODE == 0) ? Ain : (MODE == 1 ? g_ln2 : g_h1);

    const int tid  = threadIdx.x;
    const int lane = tid & 31;
    const int warp = tid >> 5;
    const int warpM = warp & 1;        // 0..1
    const int warpN = warp >> 1;       // 0..3
    const int quad = lane >> 2;        // 0..7
    const int tkid = lane & 3;         // 0..3

    const int m0 = blockIdx.y * 128;
    const int n0 = blockIdx.x * 128;

    // per-thread global/smem load slots
    // A tile: 128 rows x 16 cols = 512 float4; thread handles 2
    const int a_row0 = (tid) >> 2,        a_c0 = (tid & 3) * 4;
    const int a_row1 = (tid + 256) >> 2,  a_c1 = a_c0;   // same col pattern
    // B tile: 16 rows x 128 cols = 512 float4; thread handles 2
    const int b_r0 = tid >> 5,            b_c0 = (tid & 31) * 4;
    const int b_r1 = (tid >> 5) + 8,      b_c1 = b_c0;

    uint32_t sA = (uint32_t)__cvta_generic_to_shared(&As[0][0]);
    uint32_t sB = (uint32_t)__cvta_generic_to_shared(&Bs[0][0]);
    const uint32_t sAsz = 128 * ASTRIDE * 4;
    const uint32_t sBsz = 16 * BSTRIDE * 4;

    const int KT = K / 16;

    auto issue_tile = [&](int kt, int buf) {
        int k0 = kt * 16;
        cp_async16(sA + buf * sAsz + (a_row0 * ASTRIDE + a_c0) * 4,
                   A + (size_t)(m0 + a_row0) * K + k0 + a_c0);
        cp_async16(sA + buf * sAsz + (a_row1 * ASTRIDE + a_c1) * 4,
                   A + (size_t)(m0 + a_row1) * K + k0 + a_c1);
        cp_async16(sB + buf * sBsz + (b_r0 * BSTRIDE + b_c0) * 4,
                   Bw + (size_t)(k0 + b_r0) * N + n0 + b_c0);
        cp_async16(sB + buf * sBsz + (b_r1 * BSTRIDE + b_c1) * 4,
                   Bw + (size_t)(k0 + b_r1) * N + n0 + b_c1);
        asm volatile("cp.async.commit_group;\n");
    };

    float acc[4][4][4];
    #pragma unroll
    for (int i = 0; i < 4; i++)
        #pragma unroll
        for (int j = 0; j < 4; j++)
            #pragma unroll
            for (int r = 0; r < 4; r++) acc[i][j][r] = 0.0f;

    issue_tile(0, 0);

    for (int kt = 0; kt < KT; kt++) {
        const int buf = kt & 1;
        if (kt + 1 < KT) {
            issue_tile(kt + 1, buf ^ 1);
            asm volatile("cp.async.wait_group 1;\n");
        } else {
            asm volatile("cp.async.wait_group 0;\n");
        }
        __syncthreads();

        const float* Ab = &As[buf][0];
        const float* Bbp = &Bs[buf][0];

        #pragma unroll
        for (int ks = 0; ks < 2; ks++) {
            const int kb = ks * 8;
            uint32_t afr[4][4];
            #pragma unroll
            for (int tm = 0; tm < 4; tm++) {
                int mr = warpM * 64 + tm * 16 + quad;
                afr[tm][0] = f2tf32(Ab[(mr    ) * ASTRIDE + kb + tkid    ]);
                afr[tm][1] = f2tf32(Ab[(mr + 8) * ASTRIDE + kb + tkid    ]);
                afr[tm][2] = f2tf32(Ab[(mr    ) * ASTRIDE + kb + tkid + 4]);
                afr[tm][3] = f2tf32(Ab[(mr + 8) * ASTRIDE + kb + tkid + 4]);
            }
            uint32_t bfr[4][2];
            #pragma unroll
            for (int tn = 0; tn < 4; tn++) {
                int nc = warpN * 32 + tn * 8 + quad;
                bfr[tn][0] = f2tf32(Bbp[(kb + tkid    ) * BSTRIDE + nc]);
                bfr[tn][1] = f2tf32(Bbp[(kb + tkid + 4) * BSTRIDE + nc]);
            }
            #pragma unroll
            for (int tm = 0; tm < 4; tm++)
                #pragma unroll
                for (int tn = 0; tn < 4; tn++) {
                    asm volatile(
                        "mma.sync.aligned.m16n8k8.row.col.f32.tf32.tf32.f32 "
                        "{%0,%1,%2,%3},{%4,%5,%6,%7},{%8,%9},{%0,%1,%2,%3};"
                        : "+f"(acc[tm][tn][0]), "+f"(acc[tm][tn][1]),
                          "+f"(acc[tm][tn][2]), "+f"(acc[tm][tn][3])
                        : "r"(afr[tm][0]), "r"(afr[tm][1]),
                          "r"(afr[tm][2]), "r"(afr[tm][3]),
                          "r"(bfr[tn][0]), "r"(bfr[tn][1]));
                }
        }
        __syncthreads();
    }

    // ---------------- epilogue ----------------
    float* qkv_out = (MODE == 0)
        ? (which == 0 ? g_q : (which == 1 ? g_k : g_v)) : nullptr;

    #pragma unroll
    for (int tm = 0; tm < 4; tm++) {
        #pragma unroll
        for (int tn = 0; tn < 4; tn++) {
            #pragma unroll
            for (int r = 0; r < 4; r++) {
                int m = m0 + warpM * 64 + tm * 16 + quad + (r >= 2 ? 8 : 0);
                int n = n0 + warpN * 32 + tn * 8 + tkid * 2 + (r & 1);
                float val = acc[tm][tn][r] + bias[n];
                if (MODE == 0) {
                    int b = m >> 10, s = m & 1023;
                    int h = n >> 6, hd = n & 63;
                    qkv_out[(((size_t)b * Hh + h) * Ss + s) * HDd + hd] = val;
                } else if (MODE == 1) {
                    g_h1[(size_t)m * N + n] = gelu_exact(val);
                } else {
                    Cout[(size_t)m * N + n] =
                        gelu_exact(val) + g_y[(size_t)m * N + n];
                }
            }
        }
    }
}

// ---------------- Attention: flash-style, 1 thread = 1 query row ------------
__global__ __launch_bounds__(128) void attn_kernel(void)
{
    const int bh = blockIdx.y;
    const int tid = threadIdx.x;
    const int qrow = blockIdx.x * 128 + tid;

    const float* qp = g_q + ((size_t)bh * Ss + qrow) * HDd;
    const float* kbase = g_k + (size_t)bh * Ss * HDd;
    const float* vbase = g_v + (size_t)bh * Ss * HDd;

    float qr[HDd];
    #pragma unroll
    for (int d = 0; d < HDd; d++) qr[d] = qp[d];

    float acc[HDd] = {};
    float mi = -1e30f, li = 0.0f;

    __shared__ float Ks[16][HDd];
    __shared__ float Vs[16][HDd];

    for (int kt = 0; kt < Ss / 16; kt++) {
        const float* kp = kbase + (size_t)kt * 16 * HDd;
        const float* vp = vbase + (size_t)kt * 16 * HDd;
        #pragma unroll
        for (int l = 0; l < 8; l++) {
            int e = tid + l * 128;
            Ks[e >> 6][e & 63] = kp[e];
            Vs[e >> 6][e & 63] = vp[e];
        }
        __syncthreads();

        float sc[16];
        float tmax = -1e30f;
        #pragma unroll
        for (int j = 0; j < 16; j++) {
            float dot = 0.0f;
            #pragma unroll
            for (int d = 0; d < HDd; d++) dot += qr[d] * Ks[j][d];
            sc[j] = dot * 0.125f;
            tmax = fmaxf(tmax, sc[j]);
        }
        float mnew = fmaxf(mi, tmax);
        float corr = __expf(mi - mnew);
        li *= corr;
        #pragma unroll
        for (int d = 0; d < HDd; d++) acc[d] *= corr;
        #pragma unroll
        for (int j = 0; j < 16; j++) {
            float p = __expf(sc[j] - mnew);
            li += p;
            #pragma unroll
            for (int d = 0; d < HDd; d++) acc[d] += p * Vs[j][d];
        }
        mi = mnew;
        __syncthreads();
    }
    float inv = 1.0f / li;
    float* op = g_ctx + ((size_t)bh * Ss + qrow) * HDd;
    #pragma unroll
    for (int d = 0; d < HDd; d++) op[d] = acc[d] * inv;
}

// ---------------- LN1: y = x + LN(ctx[B,H,S,HD]) * g + b --------------------
__global__ __launch_bounds__(256) void ln1_add(
    const float* __restrict__ x, const float* __restrict__ g,
    const float* __restrict__ bta)
{
    const int row = blockIdx.x;
    const int b = row >> 10, s = row & 1023;
    const int tid = threadIdx.x;

    float vals[3];
    float sum = 0.0f, sq = 0.0f;
    #pragma unroll
    for (int i = 0; i < 3; i++) {
        int col = tid + i * 256;
        int h = col >> 6, hd = col & 63;
        float c = g_ctx[(((size_t)b * Hh + h) * Ss + s) * HDd + hd];
        vals[i] = c;
        sum += c;
        sq += c * c;
    }
    __shared__ float rs[256], rq[256];
    rs[tid] = sum; rq[tid] = sq;
    __syncthreads();
    for (int o = 128; o > 0; o >>= 1) {
        if (tid < o) { rs[tid] += rs[tid + o]; rq[tid] += rq[tid + o]; }
        __syncthreads();
    }
    float mu = rs[0] * (1.0f / Dd);
    float var = rq[0] * (1.0f / Dd) - mu * mu;
    float rstd = rsqrtf(var + 1e-5f);
    #pragma unroll
    for (int i = 0; i < 3; i++) {
        int col = tid + i * 256;
        float yv = x[(size_t)row * Dd + col] +
                   (vals[i] - mu) * rstd * g[col] + bta[col];
        g_y[(size_t)row * Dd + col] = yv;
    }
}

// ---------------- LN2: g_ln2 = LN(g_y) * g + b ------------------------------
__global__ __launch_bounds__(256) void ln2_kernel(
    const float* __restrict__ g, const float* __restrict__ bta)
{
    const int row = blockIdx.x;
    const int tid = threadIdx.x;

    float vals[3];
    float sum = 0.0f, sq = 0.0f;
    #pragma unroll
    for (int i = 0; i < 3; i++) {
        int col = tid + i * 256;
        float c = g_y[(size_t)row * Dd + col];
        vals[i] = c;
        sum += c;
        sq += c * c;
    }
    __shared__ float rs[256], rq[256];
    rs[tid] = sum; rq[tid] = sq;
    __syncthreads();
    for (int o = 128; o > 0; o >>= 1) {
        if (tid < o) { rs[tid] += rs[tid + o]; rq[tid] += rq[tid + o]; }
        __syncthreads();
    }
    float mu = rs[0] * (1.0f / Dd);
    float var = rq[0] * (1.0f / Dd) - mu * mu;
    float rstd = rsqrtf(var + 1e-5f);
    #pragma unroll
    for (int i = 0; i < 3; i++) {
        int col = tid + i * 256;
        g_ln2[(size_t)row * Dd + col] = (vals[i] - mu) * rstd * g[col] + bta[col];
    }
}

// ---------------- launch ----------------------------------------------------
extern "C" void kernel_launch(void* const* d_in, const int* in_sizes, int n_in,
                              void* d_out, int out_size)
{
    (void)in_sizes; (void)n_in; (void)out_size;
    const float* x     = (const float*)d_in[0];
    const float* wq    = (const float*)d_in[1];
    const float* bq    = (const float*)d_in[2];
    const float* wk    = (const float*)d_in[3];
    const float* bk    = (const float*)d_in[4];
    const float* wv    = (const float*)d_in[5];
    const float* bv    = (const float*)d_in[6];
    const float* ln1_g = (const float*)d_in[7];
    const float* ln1_b = (const float*)d_in[8];
    const float* ln2_g = (const float*)d_in[9];
    const float* ln2_b = (const float*)d_in[10];
    const float* w_in  = (const float*)d_in[11];
    const float* b_in  = (const float*)d_in[12];
    const float* w_out = (const float*)d_in[13];
    const float* b_out = (const float*)d_in[14];
    float* out = (float*)d_out;

    // 1) QKV projections (tf32 mma) -> [B,H,S,HD]
    dim3 gq(Dd / 128, Mm / 128);
    gemm_tf32<0><<<gq, 256>>>(x, wq, bq, nullptr, Dd, Dd, 0);
    gemm_tf32<0><<<gq, 256>>>(x, wk, bk, nullptr, Dd, Dd, 1);
    gemm_tf32<0><<<gq, 256>>>(x, wv, bv, nullptr, Dd, Dd, 2);

    // 2) attention -> g_ctx [B,H,S,HD]
    dim3 ga(Ss / 128, Bb * Hh);
    attn_kernel<<<ga, 128>>>();

    // 3) y = x + LN1(ctx)
    ln1_add<<<Mm, 256>>>(x, ln1_g, ln1_b);

    // 4) ln2 = LN2(y)
    ln2_kernel<<<Mm, 256>>>(ln2_g, ln2_b);

    // 5) h1 = gelu(ln2 @ w_in + b_in)   (tf32 mma)
    dim3 g1(HIDh / 128, Mm / 128);
    gemm_tf32<1><<<g1, 256>>>(nullptr, w_in, b_in, nullptr, HIDh, Dd, 0);

    // 6) out = y + gelu(h1 @ w_out + b_out)   (tf32 mma)
    dim3 g2(Dd / 128, Mm / 128);
    gemm_tf32<2><<<g2, 256>>>(nullptr, w_out, b_out, out, Dd, HIDh, 0);
}

// round 3
// speedup vs baseline: 4.4594x; 1.6318x over previous
#include <cuda_runtime.h>
#include <math.h>
#include <stdint.h>

#define Bb   8
#define Ss   1024
#define Dd   768
#define Hh   12
#define HDd  64
#define HIDh 3072
#define Mm   (Bb*Ss)   // 8192

// ---------------- scratch (device globals; no allocs allowed) ----------------
__device__ float g_q  [(size_t)Mm*Dd];
__device__ float g_k  [(size_t)Mm*Dd];
__device__ float g_v  [(size_t)Mm*Dd];
__device__ float g_ctx[(size_t)Mm*Dd];
__device__ float g_y  [(size_t)Mm*Dd];
__device__ float g_ln2[(size_t)Mm*Dd];
__device__ float g_h1 [(size_t)Mm*HIDh];

__device__ __forceinline__ float gelu_exact(float x) {
    return 0.5f * x * (1.0f + erff(x * 0.70710678118654752f));
}

__device__ __forceinline__ uint32_t f2tf32(float f) {
    uint32_t r;
    asm("cvt.rna.tf32.f32 %0, %1;" : "=r"(r) : "f"(f));
    return r;
}

__device__ __forceinline__ void cp_async16(uint32_t saddr, const float* gaddr) {
    asm volatile("cp.async.cg.shared.global [%0], [%1], 16;\n" :: "r"(saddr), "l"(gaddr));
}

__device__ __forceinline__ void mma_tf32(float* c, const uint32_t* a,
                                         uint32_t b0, uint32_t b1) {
    asm volatile(
        "mma.sync.aligned.m16n8k8.row.col.f32.tf32.tf32.f32 "
        "{%0,%1,%2,%3},{%4,%5,%6,%7},{%8,%9},{%0,%1,%2,%3};"
        : "+f"(c[0]), "+f"(c[1]), "+f"(c[2]), "+f"(c[3])
        : "r"(a[0]), "r"(a[1]), "r"(a[2]), "r"(a[3]), "r"(b0), "r"(b1));
}

// =====================================================================
// TF32 tensor-core GEMM (unchanged from round 2; validated)
// =====================================================================
#define ASTRIDE 20
#define BSTRIDE 136

template<int MODE>
__global__ __launch_bounds__(256) void gemm_tf32(
    const float* __restrict__ Ain, const float* __restrict__ Bw,
    const float* __restrict__ bias, float* __restrict__ Cout,
    int N, int K, int which)
{
    __shared__ float As[2][128 * ASTRIDE];
    __shared__ float Bs[2][16 * BSTRIDE];

    const float* A = (MODE == 0) ? Ain : (MODE == 1 ? g_ln2 : g_h1);

    const int tid  = threadIdx.x;
    const int lane = tid & 31;
    const int warp = tid >> 5;
    const int warpM = warp & 1;
    const int warpN = warp >> 1;
    const int quad = lane >> 2;
    const int tkid = lane & 3;

    const int m0 = blockIdx.y * 128;
    const int n0 = blockIdx.x * 128;

    const int a_row0 = (tid) >> 2,        a_c0 = (tid & 3) * 4;
    const int a_row1 = (tid + 256) >> 2,  a_c1 = a_c0;
    const int b_r0 = tid >> 5,            b_c0 = (tid & 31) * 4;
    const int b_r1 = (tid >> 5) + 8,      b_c1 = b_c0;

    uint32_t sA = (uint32_t)__cvta_generic_to_shared(&As[0][0]);
    uint32_t sB = (uint32_t)__cvta_generic_to_shared(&Bs[0][0]);
    const uint32_t sAsz = 128 * ASTRIDE * 4;
    const uint32_t sBsz = 16 * BSTRIDE * 4;

    const int KT = K / 16;

    auto issue_tile = [&](int kt, int buf) {
        int k0 = kt * 16;
        cp_async16(sA + buf * sAsz + (a_row0 * ASTRIDE + a_c0) * 4,
                   A + (size_t)(m0 + a_row0) * K + k0 + a_c0);
        cp_async16(sA + buf * sAsz + (a_row1 * ASTRIDE + a_c1) * 4,
                   A + (size_t)(m0 + a_row1) * K + k0 + a_c1);
        cp_async16(sB + buf * sBsz + (b_r0 * BSTRIDE + b_c0) * 4,
                   Bw + (size_t)(k0 + b_r0) * N + n0 + b_c0);
        cp_async16(sB + buf * sBsz + (b_r1 * BSTRIDE + b_c1) * 4,
                   Bw + (size_t)(k0 + b_r1) * N + n0 + b_c1);
        asm volatile("cp.async.commit_group;\n");
    };

    float acc[4][4][4];
    #pragma unroll
    for (int i = 0; i < 4; i++)
        #pragma unroll
        for (int j = 0; j < 4; j++)
            #pragma unroll
            for (int r = 0; r < 4; r++) acc[i][j][r] = 0.0f;

    issue_tile(0, 0);

    for (int kt = 0; kt < KT; kt++) {
        const int buf = kt & 1;
        if (kt + 1 < KT) {
            issue_tile(kt + 1, buf ^ 1);
            asm volatile("cp.async.wait_group 1;\n");
        } else {
            asm volatile("cp.async.wait_group 0;\n");
        }
        __syncthreads();

        const float* Ab = &As[buf][0];
        const float* Bbp = &Bs[buf][0];

        #pragma unroll
        for (int ks = 0; ks < 2; ks++) {
            const int kb = ks * 8;
            uint32_t afr[4][4];
            #pragma unroll
            for (int tm = 0; tm < 4; tm++) {
                int mr = warpM * 64 + tm * 16 + quad;
                afr[tm][0] = f2tf32(Ab[(mr    ) * ASTRIDE + kb + tkid    ]);
                afr[tm][1] = f2tf32(Ab[(mr + 8) * ASTRIDE + kb + tkid    ]);
                afr[tm][2] = f2tf32(Ab[(mr    ) * ASTRIDE + kb + tkid + 4]);
                afr[tm][3] = f2tf32(Ab[(mr + 8) * ASTRIDE + kb + tkid + 4]);
            }
            uint32_t bfr[4][2];
            #pragma unroll
            for (int tn = 0; tn < 4; tn++) {
                int nc = warpN * 32 + tn * 8 + quad;
                bfr[tn][0] = f2tf32(Bbp[(kb + tkid    ) * BSTRIDE + nc]);
                bfr[tn][1] = f2tf32(Bbp[(kb + tkid + 4) * BSTRIDE + nc]);
            }
            #pragma unroll
            for (int tm = 0; tm < 4; tm++)
                #pragma unroll
                for (int tn = 0; tn < 4; tn++)
                    mma_tf32(acc[tm][tn], afr[tm], bfr[tn][0], bfr[tn][1]);
        }
        __syncthreads();
    }

    float* qkv_out = (MODE == 0)
        ? (which == 0 ? g_q : (which == 1 ? g_k : g_v)) : nullptr;

    #pragma unroll
    for (int tm = 0; tm < 4; tm++) {
        #pragma unroll
        for (int tn = 0; tn < 4; tn++) {
            #pragma unroll
            for (int r = 0; r < 4; r++) {
                int m = m0 + warpM * 64 + tm * 16 + quad + (r >= 2 ? 8 : 0);
                int n = n0 + warpN * 32 + tn * 8 + tkid * 2 + (r & 1);
                float val = acc[tm][tn][r] + bias[n];
                if (MODE == 0) {
                    int b = m >> 10, s = m & 1023;
                    int h = n >> 6, hd = n & 63;
                    qkv_out[(((size_t)b * Hh + h) * Ss + s) * HDd + hd] = val;
                } else if (MODE == 1) {
                    g_h1[(size_t)m * N + n] = gelu_exact(val);
                } else {
                    Cout[(size_t)m * N + n] =
                        gelu_exact(val) + g_y[(size_t)m * N + n];
                }
            }
        }
    }
}

// =====================================================================
// Tensor-core flash attention (tf32 mma).
// Block = 64 query rows of one (b,h); 4 warps x 16 rows.
// KV tiles of 32 rows, double-buffered cp.async.
// =====================================================================
#define KSTR 68
#define PSTR 36

__global__ __launch_bounds__(128) void attn_tc(void)
{
    __shared__ float Ks[2][32 * KSTR];
    __shared__ float Vs[2][32 * KSTR];
    __shared__ float Pb[4][16 * PSTR];

    const int bh   = blockIdx.y;
    const int tid  = threadIdx.x;
    const int warp = tid >> 5;
    const int lane = tid & 31;
    const int quad = lane >> 2;     // 0..7  (row within m16 group)
    const int tkid = lane & 3;      // 0..3

    const int q0 = blockIdx.x * 64 + warp * 16;
    const float* qbase = g_q + ((size_t)bh * Ss + q0) * HDd;
    const float* kbase = g_k + (size_t)bh * Ss * HDd;
    const float* vbase = g_v + (size_t)bh * Ss * HDd;

    // Q fragments (scale 1/8 folded in; exact, power of 2)
    uint32_t qf[8][4];
    #pragma unroll
    for (int kk = 0; kk < 8; kk++) {
        int c = kk * 8 + tkid;
        qf[kk][0] = f2tf32(qbase[(quad    ) * HDd + c    ] * 0.125f);
        qf[kk][1] = f2tf32(qbase[(quad + 8) * HDd + c    ] * 0.125f);
        qf[kk][2] = f2tf32(qbase[(quad    ) * HDd + c + 4] * 0.125f);
        qf[kk][3] = f2tf32(qbase[(quad + 8) * HDd + c + 4] * 0.125f);
    }

    float o[8][4];
    #pragma unroll
    for (int j = 0; j < 8; j++)
        #pragma unroll
        for (int r = 0; r < 4; r++) o[j][r] = 0.0f;
    float mrow[2] = {-1e30f, -1e30f};
    float lrow[2] = {0.0f, 0.0f};

    uint32_t sK = (uint32_t)__cvta_generic_to_shared(&Ks[0][0]);
    uint32_t sV = (uint32_t)__cvta_generic_to_shared(&Vs[0][0]);
    const uint32_t bufsz = 32 * KSTR * 4;

    auto load_tile = [&](int t, int buf) {
        const float* kp = kbase + (size_t)t * 32 * HDd;
        const float* vp = vbase + (size_t)t * 32 * HDd;
        #pragma unroll
        for (int i = 0; i < 4; i++) {
            int idx = tid + i * 128;           // 0..511 float4 slots
            int r = idx >> 4, c4 = (idx & 15) * 4;
            cp_async16(sK + buf * bufsz + (r * KSTR + c4) * 4, kp + r * HDd + c4);
            cp_async16(sV + buf * bufsz + (r * KSTR + c4) * 4, vp + r * HDd + c4);
        }
        asm volatile("cp.async.commit_group;\n");
    };

    load_tile(0, 0);
    const int NT = Ss / 32;

    for (int t = 0; t < NT; t++) {
        const int buf = t & 1;
        if (t + 1 < NT) {
            load_tile(t + 1, buf ^ 1);
            asm volatile("cp.async.wait_group 1;\n");
        } else {
            asm volatile("cp.async.wait_group 0;\n");
        }
        __syncthreads();

        // --- S = Q @ K^T (pre-scaled) : sc[4 n-tiles][4 regs] ---
        float sc[4][4];
        #pragma unroll
        for (int j = 0; j < 4; j++)
            #pragma unroll
            for (int r = 0; r < 4; r++) sc[j][r] = 0.0f;

        #pragma unroll
        for (int kk = 0; kk < 8; kk++) {
            #pragma unroll
            for (int j = 0; j < 4; j++) {
                const float* kr = &Ks[buf][(j * 8 + quad) * KSTR + kk * 8 + tkid];
                uint32_t b0 = f2tf32(kr[0]);
                uint32_t b1 = f2tf32(kr[4]);
                mma_tf32(sc[j], qf[kk], b0, b1);
            }
        }

        // --- online softmax (rows: group0 = quad, group1 = quad+8) ---
        #pragma unroll
        for (int r = 0; r < 2; r++) {
            float tmax = -1e30f;
            #pragma unroll
            for (int j = 0; j < 4; j++)
                tmax = fmaxf(tmax, fmaxf(sc[j][2 * r], sc[j][2 * r + 1]));
            tmax = fmaxf(tmax, __shfl_xor_sync(0xffffffffu, tmax, 1));
            tmax = fmaxf(tmax, __shfl_xor_sync(0xffffffffu, tmax, 2));

            float mnew = fmaxf(mrow[r], tmax);
            float corr = __expf(mrow[r] - mnew);
            mrow[r] = mnew;
            lrow[r] *= corr;
            #pragma unroll
            for (int j = 0; j < 8; j++) {
                o[j][2 * r]     *= corr;
                o[j][2 * r + 1] *= corr;
            }
        }

        __syncwarp();   // previous tile's Pb reads done before overwrite
        float* pw = &Pb[warp][0];
        #pragma unroll
        for (int j = 0; j < 4; j++) {
            float p0 = __expf(sc[j][0] - mrow[0]);
            float p1 = __expf(sc[j][1] - mrow[0]);
            float p2 = __expf(sc[j][2] - mrow[1]);
            float p3 = __expf(sc[j][3] - mrow[1]);
            lrow[0] += p0 + p1;
            lrow[1] += p2 + p3;
            int col = j * 8 + tkid * 2;
            *(float2*)&pw[(quad    ) * PSTR + col] = make_float2(p0, p1);
            *(float2*)&pw[(quad + 8) * PSTR + col] = make_float2(p2, p3);
        }
        __syncwarp();

        // --- O += P @ V ---
        #pragma unroll
        for (int kk = 0; kk < 4; kk++) {
            uint32_t af[4];
            int c = kk * 8 + tkid;
            af[0] = f2tf32(pw[(quad    ) * PSTR + c    ]);
            af[1] = f2tf32(pw[(quad + 8) * PSTR + c    ]);
            af[2] = f2tf32(pw[(quad    ) * PSTR + c + 4]);
            af[3] = f2tf32(pw[(quad + 8) * PSTR + c + 4]);
            #pragma unroll
            for (int j = 0; j < 8; j++) {
                const float* vr = &Vs[buf][(kk * 8 + tkid) * KSTR + j * 8 + quad];
                uint32_t b0 = f2tf32(vr[0]);
                uint32_t b1 = f2tf32(vr[4 * KSTR]);
                mma_tf32(o[j], af, b0, b1);
            }
        }
        __syncthreads();
    }

    // --- finalize ---
    #pragma unroll
    for (int r = 0; r < 2; r++) {
        lrow[r] += __shfl_xor_sync(0xffffffffu, lrow[r], 1);
        lrow[r] += __shfl_xor_sync(0xffffffffu, lrow[r], 2);
    }
    float inv0 = 1.0f / lrow[0];
    float inv1 = 1.0f / lrow[1];

    float* ob0 = g_ctx + ((size_t)bh * Ss + q0 + quad    ) * HDd;
    float* ob1 = g_ctx + ((size_t)bh * Ss + q0 + quad + 8) * HDd;
    #pragma unroll
    for (int j = 0; j < 8; j++) {
        int col = j * 8 + tkid * 2;
        *(float2*)&ob0[col] = make_float2(o[j][0] * inv0, o[j][1] * inv0);
        *(float2*)&ob1[col] = make_float2(o[j][2] * inv1, o[j][3] * inv1);
    }
}

// ---------------- LN1: y = x + LN(ctx[B,H,S,HD]) * g + b --------------------
__global__ __launch_bounds__(256) void ln1_add(
    const float* __restrict__ x, const float* __restrict__ g,
    const float* __restrict__ bta)
{
    const int row = blockIdx.x;
    const int b = row >> 10, s = row & 1023;
    const int tid = threadIdx.x;

    float vals[3];
    float sum = 0.0f, sq = 0.0f;
    #pragma unroll
    for (int i = 0; i < 3; i++) {
        int col = tid + i * 256;
        int h = col >> 6, hd = col & 63;
        float c = g_ctx[(((size_t)b * Hh + h) * Ss + s) * HDd + hd];
        vals[i] = c;
        sum += c;
        sq += c * c;
    }
    __shared__ float rs[256], rq[256];
    rs[tid] = sum; rq[tid] = sq;
    __syncthreads();
    for (int o = 128; o > 0; o >>= 1) {
        if (tid < o) { rs[tid] += rs[tid + o]; rq[tid] += rq[tid + o]; }
        __syncthreads();
    }
    float mu = rs[0] * (1.0f / Dd);
    float var = rq[0] * (1.0f / Dd) - mu * mu;
    float rstd = rsqrtf(var + 1e-5f);
    #pragma unroll
    for (int i = 0; i < 3; i++) {
        int col = tid + i * 256;
        float yv = x[(size_t)row * Dd + col] +
                   (vals[i] - mu) * rstd * g[col] + bta[col];
        g_y[(size_t)row * Dd + col] = yv;
    }
}

// ---------------- LN2: g_ln2 = LN(g_y) * g + b ------------------------------
__global__ __launch_bounds__(256) void ln2_kernel(
    const float* __restrict__ g, const float* __restrict__ bta)
{
    const int row = blockIdx.x;
    const int tid = threadIdx.x;

    float vals[3];
    float sum = 0.0f, sq = 0.0f;
    #pragma unroll
    for (int i = 0; i < 3; i++) {
        int col = tid + i * 256;
        float c = g_y[(size_t)row * Dd + col];
        vals[i] = c;
        sum += c;
        sq += c * c;
    }
    __shared__ float rs[256], rq[256];
    rs[tid] = sum; rq[tid] = sq;
    __syncthreads();
    for (int o = 128; o > 0; o >>= 1) {
        if (tid < o) { rs[tid] += rs[tid + o]; rq[tid] += rq[tid + o]; }
        __syncthreads();
    }
    float mu = rs[0] * (1.0f / Dd);
    float var = rq[0] * (1.0f / Dd) - mu * mu;
    float rstd = rsqrtf(var + 1e-5f);
    #pragma unroll
    for (int i = 0; i < 3; i++) {
        int col = tid + i * 256;
        g_ln2[(size_t)row * Dd + col] = (vals[i] - mu) * rstd * g[col] + bta[col];
    }
}

// ---------------- launch ----------------------------------------------------
extern "C" void kernel_launch(void* const* d_in, const int* in_sizes, int n_in,
                              void* d_out, int out_size)
{
    (void)in_sizes; (void)n_in; (void)out_size;
    const float* x     = (const float*)d_in[0];
    const float* wq    = (const float*)d_in[1];
    const float* bq    = (const float*)d_in[2];
    const float* wk    = (const float*)d_in[3];
    const float* bk    = (const float*)d_in[4];
    const float* wv    = (const float*)d_in[5];
    const float* bv    = (const float*)d_in[6];
    const float* ln1_g = (const float*)d_in[7];
    const float* ln1_b = (const float*)d_in[8];
    const float* ln2_g = (const float*)d_in[9];
    const float* ln2_b = (const float*)d_in[10];
    const float* w_in  = (const float*)d_in[11];
    const float* b_in  = (const float*)d_in[12];
    const float* w_out = (const float*)d_in[13];
    const float* b_out = (const float*)d_in[14];
    float* out = (float*)d_out;

    dim3 gq(Dd / 128, Mm / 128);
    gemm_tf32<0><<<gq, 256>>>(x, wq, bq, nullptr, Dd, Dd, 0);
    gemm_tf32<0><<<gq, 256>>>(x, wk, bk, nullptr, Dd, Dd, 1);
    gemm_tf32<0><<<gq, 256>>>(x, wv, bv, nullptr, Dd, Dd, 2);

    dim3 ga(Ss / 64, Bb * Hh);
    attn_tc<<<ga, 128>>>();

    ln1_add<<<Mm, 256>>>(x, ln1_g, ln1_b);
    ln2_kernel<<<Mm, 256>>>(ln2_g, ln2_b);

    dim3 g1(HIDh / 128, Mm / 128);
    gemm_tf32<1><<<g1, 256>>>(nullptr, w_in, b_in, nullptr, HIDh, Dd, 0);

    dim3 g2(Dd / 128, Mm / 128);
    gemm_tf32<2><<<g2, 256>>>(nullptr, w_out, b_out, out, Dd, HIDh, 0);
}